// round 3
// baseline (speedup 1.0000x reference)
#include <cuda_runtime.h>
#include <math.h>

typedef unsigned long long ull;

// Problem constants
#define DD 256
#define PP 64
#define TINV 10.0f

// Output offsets (floats): routing(65536) | routes(67108864) | tw(65536) | ps(4194304)
#define OFF_ROUTING 0LL
#define OFF_ROUTES  65536LL
#define OFF_TW      67174400LL
#define OFF_PS      67239936LL

#define N_GEMM 512
#define GRID_TOTAL 8768

// GEMM tiling: CTA 128 rows x 64 patterns, KC=32 per chunk, 8 chunks, 2-stage cp.async
#define KC 32
#define PITCH_A 36                 // 144B row stride (16B aligned, bank-clean for row stride 1)
#define A_BUF (128 * PITCH_A)      // floats per A stage
#define B_BUF (KC * PP)            // floats per B stage
#define SMEM_FLOATS (2 * A_BUF + 2 * B_BUF)
#define SMEM_BYTES  (SMEM_FLOATS * 4)   // 53248 B -> 3 CTAs/SM

// Normalized patterns, k-major: g_patT[k*64 + p]
__device__ float g_patT[DD * PP];

__global__ void normalize_patterns_kernel(const float* __restrict__ patterns) {
    int p = threadIdx.x;
    if (p >= PP) return;
    float ss = 0.0f;
    #pragma unroll 8
    for (int k = 0; k < DD; k++) {
        float v = patterns[p * DD + k];
        ss = fmaf(v, v, ss);
    }
    float inv = 1.0f / fmaxf(sqrtf(ss), 1e-12f);
    for (int k = 0; k < DD; k++)
        g_patT[k * PP + p] = patterns[p * DD + k] * inv;
}

// ---- packed fp32 + async-copy helpers ----
__device__ __forceinline__ void fma2(ull& d, ull a, ull b) {
    asm("fma.rn.f32x2 %0, %1, %2, %3;" : "=l"(d) : "l"(a), "l"(b), "l"(d));
}
__device__ __forceinline__ ull splat2(float x) {
    ull r; unsigned int u = __float_as_uint(x);
    asm("mov.b64 %0, {%1, %1};" : "=l"(r) : "r"(u));
    return r;
}
__device__ __forceinline__ void unpack2(ull v, float& lo, float& hi) {
    unsigned int l, h;
    asm("mov.b64 {%0, %1}, %2;" : "=r"(l), "=r"(h) : "l"(v));
    lo = __uint_as_float(l); hi = __uint_as_float(h);
}
__device__ __forceinline__ unsigned su32(const void* p) {
    return (unsigned)__cvta_generic_to_shared(p);
}
#define CP16(dst, src) asm volatile("cp.async.cg.shared.global [%0], [%1], 16;\n" :: "r"(dst), "l"(src))
#define CP_COMMIT()    asm volatile("cp.async.commit_group;\n" ::: "memory")
#define CP_WAIT1()     asm volatile("cp.async.wait_group 1;\n" ::: "memory")
#define CP_WAIT0()     asm volatile("cp.async.wait_group 0;\n" ::: "memory")

// ---------------------------------------------------------------------------
// Fused kernel: GEMM+softmax tiles interleaved with DRAM-bound fill CTAs.
// ---------------------------------------------------------------------------
__global__ __launch_bounds__(256, 3)
void fused_kernel(const float* __restrict__ states,
                  const float* __restrict__ tw_in,
                  float* __restrict__ out) {
    extern __shared__ float smem[];
    int bid = blockIdx.x;
    int tid = threadIdx.x;

    bool isGemm = (bid < 17 * N_GEMM) && (bid % 17 == 0);

    if (!isGemm) {
        long long fillIdx = (bid < 17 * N_GEMM) ? (bid - (bid + 16) / 17)
                                                : (bid - N_GEMM);
        if (fillIdx < 8192) {
            // optimal_routes: v[..., j] = -(float)j/1024 exactly
            float4* out4 = (float4*)(out + OFF_ROUTES);
            long long base = fillIdx * 2048;
            const float r = 1.0f / 1024.0f;
            #pragma unroll
            for (int it = 0; it < 8; it++) {
                long long q = base + it * 256 + tid;
                int c = (int)(q & 255) << 2;
                float4 v;
                v.x = -(float)(c + 0) * r;
                v.y = -(float)(c + 1) * r;
                v.z = -(float)(c + 2) * r;
                v.w = -(float)(c + 3) * r;
                __stcs(&out4[q], v);
            }
        } else {
            int i4 = (int)(fillIdx - 8192) * 256 + tid;
            const float r = 1.0f / 1024.0f;
            ((float4*)(out + OFF_ROUTING))[i4] = make_float4(r, r, r, r);
            ((float4*)(out + OFF_TW))[i4] = ((const float4*)tw_in)[i4];
        }
        return;
    }

    // ---------------- GEMM + softmax tile ----------------
    int gemmIdx = bid / 17;
    long long rowBase = (long long)gemmIdx * 128;
    const float* A = states + rowBase * DD;

    float* sA = smem;                 // [2][128][PITCH_A] row-major
    float* sB = smem + 2 * A_BUF;     // [2][KC][64] k-major

    int px = tid & 7;    // pattern group: px*8 .. px*8+7 (4 packed pattern-pairs)
    int ry = tid >> 3;   // rows: ry, ry+32, ry+64, ry+96

    // cp.async staging assignments (all 16B segments)
    //   A chunk: 128 rows x 32 k = 1024 segs; 4 per thread
    //   B chunk:  32 k  x 64 p  =  512 segs; 2 per thread
    unsigned aDst[4]; const float* aSrc[4];
    #pragma unroll
    for (int j = 0; j < 4; j++) {
        int i   = tid + j * 256;
        int row = i >> 3;
        int seg = i & 7;
        aSrc[j] = A + (long long)row * DD + seg * 4;
        aDst[j] = su32(sA + row * PITCH_A + seg * 4);
    }
    unsigned bDst[2]; const float* bSrc[2];
    #pragma unroll
    for (int j = 0; j < 2; j++) {
        int i    = tid + j * 256;
        int krow = i >> 4;
        int seg  = i & 15;
        bSrc[j] = g_patT + krow * PP + seg * 4;
        bDst[j] = su32(sB + krow * PP + seg * 4);
    }

    ull acc[4][4];
    #pragma unroll
    for (int j = 0; j < 4; j++)
        #pragma unroll
        for (int q = 0; q < 4; q++) acc[j][q] = 0ULL;

    const int NCH = DD / KC;  // 8

    // stage chunk 0 into buffer 0
    #pragma unroll
    for (int j = 0; j < 4; j++) CP16(aDst[j], aSrc[j]);
    #pragma unroll
    for (int j = 0; j < 2; j++) CP16(bDst[j], bSrc[j]);
    CP_COMMIT();

    for (int c = 0; c < NCH; c++) {
        int nb = (c + 1) & 1;
        if (c + 1 < NCH) {
            unsigned aOff = nb * A_BUF * 4;
            unsigned bOff = nb * B_BUF * 4;
            int kOff = (c + 1) * KC;
            #pragma unroll
            for (int j = 0; j < 4; j++) CP16(aDst[j] + aOff, aSrc[j] + kOff);
            #pragma unroll
            for (int j = 0; j < 2; j++) CP16(bDst[j] + bOff, bSrc[j] + kOff * PP);
            CP_COMMIT();
            CP_WAIT1();
        } else {
            CP_WAIT0();
        }
        __syncthreads();

        const float* a = sA + (c & 1) * A_BUF + ry * PITCH_A;
        const float* b = sB + (c & 1) * B_BUF + px * 8;
        #pragma unroll 8
        for (int k = 0; k < KC; k++) {
            ulonglong2 b01 = *(const ulonglong2*)(b + k * PP);
            ulonglong2 b23 = *(const ulonglong2*)(b + k * PP + 4);
            #pragma unroll
            for (int j = 0; j < 4; j++) {
                ull as = splat2(a[j * 32 * PITCH_A + k]);
                fma2(acc[j][0], as, b01.x);
                fma2(acc[j][1], as, b01.y);
                fma2(acc[j][2], as, b23.x);
                fma2(acc[j][3], as, b23.y);
            }
        }
        __syncthreads();
    }

    // Epilogue: scores into smem [128][65]
    float* sS = smem;
    #pragma unroll
    for (int j = 0; j < 4; j++) {
        int row = ry + 32 * j;
        #pragma unroll
        for (int q = 0; q < 4; q++) {
            float lo, hi;
            unpack2(acc[j][q], lo, hi);
            sS[row * 65 + px * 8 + 2 * q + 0] = lo;
            sS[row * 65 + px * 8 + 2 * q + 1] = hi;
        }
    }
    __syncthreads();

    if (tid < 128) {
        float* rowp = &sS[tid * 65];
        float mx = -1e30f;
        #pragma unroll
        for (int p = 0; p < PP; p++) mx = fmaxf(mx, rowp[p]);
        mx *= TINV;
        float sum = 0.0f;
        #pragma unroll
        for (int p = 0; p < PP; p++) {
            float e = __expf(rowp[p] * TINV - mx);
            rowp[p] = e;
            sum += e;
        }
        float inv = 1.0f / sum;
        #pragma unroll
        for (int p = 0; p < PP; p++) rowp[p] *= inv;
    }
    __syncthreads();

    float* O = out + OFF_PS + rowBase * PP;
    for (int i = tid; i < 128 * PP / 4; i += 256) {
        int row = i >> 4, pq = (i & 15) << 2;
        float4 v = make_float4(sS[row * 65 + pq + 0],
                               sS[row * 65 + pq + 1],
                               sS[row * 65 + pq + 2],
                               sS[row * 65 + pq + 3]);
        *(float4*)&O[row * PP + pq] = v;
    }
}

extern "C" void kernel_launch(void* const* d_in, const int* in_sizes, int n_in,
                              void* d_out, int out_size) {
    const float* states   = (const float*)d_in[0];  // (4,16,1024,256)
    const float* patterns = (const float*)d_in[1];  // (64,256)
    const float* tw       = (const float*)d_in[2];  // (16,64,64)
    float* out = (float*)d_out;

    cudaFuncSetAttribute(fused_kernel,
                         cudaFuncAttributeMaxDynamicSharedMemorySize,
                         SMEM_BYTES);

    normalize_patterns_kernel<<<1, 64>>>(patterns);
    fused_kernel<<<GRID_TOTAL, 256, SMEM_BYTES>>>(states, tw, out);
}

// round 7
// speedup vs baseline: 1.5644x; 1.5644x over previous
#include <cuda_runtime.h>
#include <math.h>
#include <stdint.h>

// Problem constants
#define DD 256
#define PP 64
#define TINV 10.0f

// Output offsets (floats): routing(65536) | routes(67108864) | tw(65536) | ps(4194304)
#define OFF_ROUTING 0LL
#define OFF_ROUTES  65536LL
#define OFF_TW      67174400LL
#define OFF_PS      67239936LL

#define N_GEMM 512          // 65536 rows / 128 rows per tile
#define GRID_TOTAL 8768

// smem (floats): [0,64) normInv | [64,192) sInv | [256, 256+128*76) sA | then sB 64*76
// epilogue overlay: sS[128][66] at sA (8448 <= 9728 floats)
#define PITCH 76
#define SA_OFF 256
#define SB_OFF (SA_OFF + 128 * PITCH)
#define SMEM_FLOATS (SB_OFF + 64 * PITCH)
#define SMEM_BYTES (SMEM_FLOATS * 4)      // 59392 B -> 3 CTAs/SM

// ---- tf32 helpers ----
__device__ __forceinline__ unsigned f2tf(float x) {
    unsigned r;
    asm("cvt.rna.tf32.f32 %0, %1;" : "=r"(r) : "f"(x));
    return r;
}
__device__ __forceinline__ void split_tf32(float x, unsigned& hi, unsigned& lo) {
    hi = f2tf(x);
    lo = f2tf(x - __uint_as_float(hi));
}
__device__ __forceinline__ void mma_tf32(float* c,
                                         unsigned a0, unsigned a1, unsigned a2, unsigned a3,
                                         unsigned b0, unsigned b1) {
    asm volatile(
        "mma.sync.aligned.m16n8k8.row.col.f32.tf32.tf32.f32 "
        "{%0,%1,%2,%3}, {%4,%5,%6,%7}, {%8,%9}, {%0,%1,%2,%3};"
        : "+f"(c[0]), "+f"(c[1]), "+f"(c[2]), "+f"(c[3])
        : "r"(a0), "r"(a1), "r"(a2), "r"(a3), "r"(b0), "r"(b1));
}

// ---------------------------------------------------------------------------
// Single fused kernel: TF32-mma GEMM+softmax tiles interleaved with fill CTAs.
// ---------------------------------------------------------------------------
__global__ __launch_bounds__(256, 3)
void fused_kernel(const float* __restrict__ states,
                  const float* __restrict__ patterns,
                  const float* __restrict__ tw_in,
                  float* __restrict__ out) {
    extern __shared__ float smem[];
    int bid = blockIdx.x;
    int tid = threadIdx.x;

    bool isGemm = (bid < 17 * N_GEMM) && (bid % 17 == 0);

    if (!isGemm) {
        long long fillIdx = (bid < 17 * N_GEMM) ? (bid - (bid + 16) / 17)
                                                : (bid - N_GEMM);
        if (fillIdx < 8192) {
            // optimal_routes: v[..., j] = -(float)j/1024 exactly
            float4* out4 = (float4*)(out + OFF_ROUTES);
            long long base = fillIdx * 2048;
            const float r = 1.0f / 1024.0f;
            #pragma unroll
            for (int it = 0; it < 8; it++) {
                long long q = base + it * 256 + tid;
                int c = (int)(q & 255) << 2;
                float4 v;
                v.x = -(float)(c + 0) * r;
                v.y = -(float)(c + 1) * r;
                v.z = -(float)(c + 2) * r;
                v.w = -(float)(c + 3) * r;
                __stcs(&out4[q], v);
            }
        } else {
            int i4 = (int)(fillIdx - 8192) * 256 + tid;
            const float r = 1.0f / 1024.0f;
            ((float4*)(out + OFF_ROUTING))[i4] = make_float4(r, r, r, r);
            ((float4*)(out + OFF_TW))[i4] = ((const float4*)tw_in)[i4];
        }
        return;
    }

    // ================ GEMM tile: 128 rows x 64 patterns, K=256 ================
    int gemmIdx = bid / 17;
    long long rowBase = (long long)gemmIdx * 128;
    const float* A = states + rowBase * DD;

    float* sNorm = smem;            // [64]
    float* sInv  = smem + 64;       // [128]
    float* sA    = smem + SA_OFF;   // [128][76]
    float* sB    = smem + SB_OFF;   // [64][76]

    // ---- pattern inverse norms (temp partials in sA region) ----
    {
        float* tmp = sA;                       // 256 floats
        int p = tid >> 2, q = tid & 3;
        const float4* pv = (const float4*)(patterns + p * DD + q * 64);
        float ss = 0.0f;
        #pragma unroll
        for (int i = 0; i < 16; i++) {
            float4 v = pv[i];
            ss = fmaf(v.x, v.x, fmaf(v.y, v.y, fmaf(v.z, v.z, fmaf(v.w, v.w, ss))));
        }
        tmp[tid] = ss;
        __syncthreads();
        if (tid < 64) {
            float s = tmp[tid * 4] + tmp[tid * 4 + 1] + tmp[tid * 4 + 2] + tmp[tid * 4 + 3];
            sNorm[tid] = 1.0f / fmaxf(sqrtf(s), 1e-12f);
        }
    }

    int w    = tid >> 5;
    int lane = tid & 31;
    int g    = lane >> 2;    // group id 0..7
    int tig  = lane & 3;     // thread in group

    float acc[8][4];
    #pragma unroll
    for (int nb = 0; nb < 8; nb++)
        #pragma unroll
        for (int i = 0; i < 4; i++) acc[nb][i] = 0.0f;

    const float* aRow0 = sA + (w * 16 + g) * PITCH;
    const float* aRow8 = aRow0 + 8 * PITCH;

    for (int c = 0; c < 4; c++) {       // 4 chunks of K=64
        __syncthreads();
        // stage A chunk: 128 rows x 64 k, 8 float4 per thread
        #pragma unroll
        for (int j = 0; j < 8; j++) {
            int i = tid + j * 256;
            int row = i >> 4, seg = i & 15;
            float4 v = *(const float4*)&A[(long long)row * DD + c * 64 + seg * 4];
            *(float4*)&sA[row * PITCH + seg * 4] = v;
        }
        // stage B chunk: 64 patterns x 64 k, normalized, 4 float4 per thread
        #pragma unroll
        for (int j = 0; j < 4; j++) {
            int i = tid + j * 256;
            int p = i >> 4, seg = i & 15;
            float inv = sNorm[p];
            float4 v = *(const float4*)&patterns[p * DD + c * 64 + seg * 4];
            v.x *= inv; v.y *= inv; v.z *= inv; v.w *= inv;
            *(float4*)&sB[p * PITCH + seg * 4] = v;
        }
        __syncthreads();

        #pragma unroll
        for (int ks = 0; ks < 8; ks++) {
            int k0 = ks * 8;
            unsigned ah0, ah1, ah2, ah3, al0, al1, al2, al3;
            split_tf32(aRow0[k0 + tig],     ah0, al0);
            split_tf32(aRow8[k0 + tig],     ah1, al1);
            split_tf32(aRow0[k0 + tig + 4], ah2, al2);
            split_tf32(aRow8[k0 + tig + 4], ah3, al3);
            #pragma unroll
            for (int nb = 0; nb < 8; nb++) {
                const float* bp = sB + (nb * 8 + g) * PITCH + k0 + tig;
                unsigned bh0, bl0, bh1, bl1;
                split_tf32(bp[0], bh0, bl0);
                split_tf32(bp[4], bh1, bl1);
                mma_tf32(acc[nb], ah0, ah1, ah2, ah3, bh0, bh1);
                mma_tf32(acc[nb], ah0, ah1, ah2, ah3, bl0, bl1);
                mma_tf32(acc[nb], al0, al1, al2, al3, bh0, bh1);
            }
        }
    }
    __syncthreads();

    // ================ epilogue: softmax over 64 patterns per row ================
    float* sS = sA;   // overlay [128][66]
    {
        int r0 = w * 16 + g;
        #pragma unroll
        for (int nb = 0; nb < 8; nb++) {
            int col = nb * 8 + 2 * tig;
            *(float2*)&sS[r0 * 66 + col]       = make_float2(acc[nb][0], acc[nb][1]);
            *(float2*)&sS[(r0 + 8) * 66 + col] = make_float2(acc[nb][2], acc[nb][3]);
        }
    }
    __syncthreads();

    if (tid < 128) {
        float* rowp = &sS[tid * 66];
        float mx = -1e30f;
        #pragma unroll
        for (int p = 0; p < PP; p++) mx = fmaxf(mx, rowp[p]);
        mx *= TINV;
        float sum = 0.0f;
        #pragma unroll
        for (int p = 0; p < PP; p++) {
            float e = __expf(rowp[p] * TINV - mx);
            rowp[p] = e;
            sum += e;
        }
        sInv[tid] = 1.0f / sum;
    }
    __syncthreads();

    // coalesced streaming store of the 128x64 tile
    float* O = out + OFF_PS + rowBase * PP;
    for (int i = tid; i < 128 * PP / 4; i += 256) {
        int row = i >> 4, pq = (i & 15) << 2;
        float inv = sInv[row];
        float4 v = make_float4(sS[row * 66 + pq + 0] * inv,
                               sS[row * 66 + pq + 1] * inv,
                               sS[row * 66 + pq + 2] * inv,
                               sS[row * 66 + pq + 3] * inv);
        __stcs((float4*)&O[row * PP + pq], v);
    }
}

extern "C" void kernel_launch(void* const* d_in, const int* in_sizes, int n_in,
                              void* d_out, int out_size) {
    const float* states   = (const float*)d_in[0];  // (4,16,1024,256)
    const float* patterns = (const float*)d_in[1];  // (64,256)
    const float* tw       = (const float*)d_in[2];  // (16,64,64)
    float* out = (float*)d_out;

    cudaFuncSetAttribute(fused_kernel,
                         cudaFuncAttributeMaxDynamicSharedMemorySize,
                         SMEM_BYTES);

    fused_kernel<<<GRID_TOTAL, 256, SMEM_BYTES>>>(states, patterns, tw, out);
}